// round 16
// baseline (speedup 1.0000x reference)
#include <cuda_runtime.h>
#include <cuda_bf16.h>
#include <stdint.h>
#include <math.h>

// ---------------------------------------------------------------------------
// Fixed problem shapes
// ---------------------------------------------------------------------------
#define BATCH 2
#define CHN   256
#define NTOT  43095
#define TOTC  3507
#define POST  300
#define NEGF  (-1e30f)
#define CLAMPF 4.135166556742356f
#define IMG   832.0f

__device__ __constant__ int   c_W[4]      = {104, 52, 26, 13};
__device__ __constant__ int   c_Nanch[4]  = {32448, 8112, 2028, 507};
__device__ __constant__ int   c_noff[4]   = {0, 32448, 40560, 42588};
__device__ __constant__ int   c_K[4]      = {1000, 1000, 1000, 507};
__device__ __constant__ int   c_cbase[4]  = {0, 1000, 2000, 3000};
__device__ __constant__ float c_stride[4] = {8.f, 16.f, 32.f, 64.f};
__device__ __constant__ float c_size[4]   = {32.f, 64.f, 128.f, 256.f};
__device__ __constant__ int   c_HTO[4]    = {0, 169, 212, 223};
__device__ __constant__ int   c_FTO[4]    = {0, 338, 423, 445};
__device__ __constant__ int   c_toff[4]   = {0, 5537792, 6922240, 7268352};

// ---------------------------------------------------------------------------
// Static device scratch
// ---------------------------------------------------------------------------
__device__ __align__(16) float g_t[7354880];
__device__ __align__(16) __nv_bfloat16 g_fh[7354880];
__device__ __align__(16) __nv_bfloat16 g_fl[7354880];
__device__ __align__(16) float g_ft3[BATCH * 169 * CHN];
__device__ float g_logits[BATCH * NTOT];
__device__ float g_deltas[BATCH * NTOT * 4];
__device__ int   g_cand_n[BATCH * TOTC];
__device__ float g_sc[BATCH * TOTC];
__device__ float g_box[BATCH * TOTC * 4];
__device__ float g_obox[BATCH * TOTC * 4];
__device__ float g_rois[BATCH * POST * 4];
__device__ __align__(16) __nv_bfloat16 g_rfh[784 * 600 * 16];
__device__ __align__(16) __nv_bfloat16 g_rfl[784 * 600 * 16];
__device__ __align__(16) float g_fcpart[4 * 600 * 1408];
__device__ __align__(16) __nv_bfloat16 g_cw2_hi[144 * 256 * 16];
__device__ __align__(16) __nv_bfloat16 g_cw2_lo[144 * 256 * 16];
__device__ __align__(16) __nv_bfloat16 g_fw2_hi[784 * 1408 * 16];
__device__ __align__(16) __nv_bfloat16 g_fw2_lo[784 * 1408 * 16];

union U8 { __nv_bfloat16 b[8]; uint4 u; };

__device__ __forceinline__ void bsplit(float x, __nv_bfloat16& h, __nv_bfloat16& l)
{
    h = __float2bfloat16_rn(x);
    l = __float2bfloat16_rn(x - __bfloat162float(h));
}

// ---------------------------------------------------------------------------
// cp.async helpers (16B, cg; zfill variant via register src-size)
// ---------------------------------------------------------------------------
#define CPA16(dst, src)                                                         \
    asm volatile("cp.async.cg.shared.global [%0], [%1], 16;"                    \
                 :: "r"(dst), "l"(src))
#define CPA16Z(dst, src, pred)                                                  \
    asm volatile("{\n\t.reg .pred q;\n\t.reg .s32 sz;\n\t"                      \
                 "setp.ne.u32 q, %2, 0;\n\tselp.s32 sz, 16, 0, q;\n\t"          \
                 "cp.async.cg.shared.global [%0], [%1], 16, sz;\n\t}"           \
                 :: "r"(dst), "l"(src), "r"((unsigned)(pred)))
#define CPA_COMMIT() asm volatile("cp.async.commit_group;")
#define CPA_WAIT1()  asm volatile("cp.async.wait_group 1;")

// GEMM dynamic smem: 3 stages x (A 2x128x24 + B 2x64x24) bf16 = 55296 B
#define GEMM_SMEM 55296
// per-stage strides in bf16 elements
#define A_ST (2 * 128 * 24)
#define B_ST (2 * 64 * 24)

// ---------------------------------------------------------------------------
// Prep kernels
// ---------------------------------------------------------------------------
__global__ void prep_wconv(const float* __restrict__ cw)
{
    int co = blockIdx.x;
    int t = threadIdx.x;
#pragma unroll
    for (int j = 0; j < 9; j++) {
        int kp = j * 256 + t;
        int ci = kp & 255, r = kp >> 8;
        float v = cw[co * 2304 + ci * 9 + r];
        size_t d = (size_t)(kp >> 4) * 4096 + co * 16 + (kp & 15);
        __nv_bfloat16 h, l;
        bsplit(v, h, l);
        g_cw2_hi[d] = h;
        g_cw2_lo[d] = l;
    }
}

__global__ void prep_fw(const float* __restrict__ fw)
{
    int idx = blockIdx.x * 256 + threadIdx.x;
    if (idx >= 784 * 1408) return;
    int kblk = idx / 1408;
    int m = idx - kblk * 1408;
    const float4* p = (const float4*)(fw + (size_t)m * 12544 + kblk * 16);
    float4 v0 = p[0], v1 = p[1], v2 = p[2], v3 = p[3];
    float xs[16] = {v0.x, v0.y, v0.z, v0.w, v1.x, v1.y, v1.z, v1.w,
                    v2.x, v2.y, v2.z, v2.w, v3.x, v3.y, v3.z, v3.w};
    U8 h0, l0, h1, l1;
#pragma unroll
    for (int i = 0; i < 8; i++) bsplit(xs[i], h0.b[i], l0.b[i]);
#pragma unroll
    for (int i = 0; i < 8; i++) bsplit(xs[8 + i], h1.b[i], l1.b[i]);
    size_t d = (size_t)kblk * 22528 + m * 16;
    *(uint4*)(g_fw2_hi + d) = h0.u;  *(uint4*)(g_fw2_hi + d + 8) = h1.u;
    *(uint4*)(g_fw2_lo + d) = l0.u;  *(uint4*)(g_fw2_lo + d + 8) = l1.u;
}

__global__ void prep_feat(
    const float* __restrict__ f0, const float* __restrict__ f1,
    const float* __restrict__ f2, const float* __restrict__ f3)
{
    __shared__ float tile[32][33];
    int bx = blockIdx.x;
    int lvl = (bx < 338) ? 0 : (bx < 423) ? 1 : (bx < 445) ? 2 : 3;
    int pix0 = (bx - c_FTO[lvl]) * 32;
    int W = c_W[lvl];
    int Np = W * W;
    const float* in = (lvl == 0) ? f0 : (lvl == 1) ? f1 : (lvl == 2) ? f2 : f3;

    int cg32 = blockIdx.y;
    int b    = blockIdx.z;
    int t    = threadIdx.x;
    int tx = t & 31, ty = t >> 5;

#pragma unroll
    for (int r = 0; r < 4; r++) {
        int cl = ty + r * 8;
        int pix = pix0 + tx;
        float v = (pix < Np) ? in[((size_t)b * 256 + cg32 * 32 + cl) * Np + pix] : 0.f;
        tile[cl][tx] = v;
    }
    __syncthreads();
    size_t lb = (size_t)c_toff[lvl] + (size_t)b * Np * 256;
#pragma unroll
    for (int r = 0; r < 4; r++) {
        int pl = ty + r * 8;
        int pix = pix0 + pl;
        if (pix < Np) {
            float v = tile[tx][pl];
            __nv_bfloat16 h, l;
            bsplit(v, h, l);
            int ch = cg32 * 32 + tx;
            size_t off = lb + ((size_t)(ch >> 4) * Np + pix) * 16 + (ch & 15);
            g_fh[off] = h;
            g_fl[off] = l;
        }
    }
}

__global__ void prep_ft3(const float* __restrict__ f3)
{
    int idx = blockIdx.x * 256 + threadIdx.x;
    if (idx >= BATCH * 169 * 256) return;
    int c = idx & 255;
    int p = (idx >> 8) % 169;
    int b = idx / (169 * 256);
    g_ft3[idx] = f3[(b * 256 + c) * 169 + p];
}

// ---------------------------------------------------------------------------
// mma machinery (warp tile 64x32, BK=16, bf16-split, fp32 accum)
// Ash(s,h,row,col) = smA + s*A_ST + h*(128*24) + row*24 + col
// Bsh(s,h,row,col) = smB + s*B_ST + h*(64*24)  + row*24 + col
// ---------------------------------------------------------------------------
#define ASH(s, h, row, col) (smA + (s) * A_ST + (h) * (128 * 24) + (row) * 24 + (col))
#define BSH(s, h, row, col) (smB + (s) * B_ST + (h) * (64 * 24) + (row) * 24 + (col))

#define LDSM4(r0, r1, r2, r3, addr)                                             \
    asm volatile("ldmatrix.sync.aligned.m8n8.x4.shared.b16 {%0,%1,%2,%3},[%4];" \
                 : "=r"(r0), "=r"(r1), "=r"(r2), "=r"(r3) : "r"(addr))

#define MMA_B16(d, a, b)                                                        \
    asm volatile("mma.sync.aligned.m16n8k16.row.col.f32.bf16.bf16.f32 "         \
                 "{%0,%1,%2,%3},{%4,%5,%6,%7},{%8,%9},{%0,%1,%2,%3};"           \
                 : "+f"(d[0]), "+f"(d[1]), "+f"(d[2]), "+f"(d[3])               \
                 : "r"(a[0]), "r"(a[1]), "r"(a[2]), "r"(a[3]),                  \
                   "r"(b[0]), "r"(b[1]))

#define GEMM_COMPUTE(bf) do {                                                   \
    uint32_t afr[2][4][4];                                                      \
    uint32_t bfr[2][4][2];                                                      \
    _Pragma("unroll")                                                           \
    for (int h = 0; h < 2; h++) {                                               \
        _Pragma("unroll")                                                       \
        for (int mt = 0; mt < 4; mt++) {                                        \
            uint32_t ad = (uint32_t)__cvta_generic_to_shared(                   \
                ASH(bf, h, mo + mt * 16 + (lane & 15), (lane >> 4) * 8));       \
            LDSM4(afr[h][mt][0], afr[h][mt][1], afr[h][mt][2], afr[h][mt][3], ad); \
        }                                                                       \
        _Pragma("unroll")                                                       \
        for (int np = 0; np < 2; np++) {                                        \
            uint32_t bd = (uint32_t)__cvta_generic_to_shared(                   \
                BSH(bf, h, no + np * 16 + (lane & 7) + ((lane & 16) >> 1), lane & 8)); \
            LDSM4(bfr[h][np * 2][0], bfr[h][np * 2][1],                         \
                  bfr[h][np * 2 + 1][0], bfr[h][np * 2 + 1][1], bd);            \
        }                                                                       \
    }                                                                           \
    _Pragma("unroll")                                                           \
    for (int mt = 0; mt < 4; mt++)                                              \
        _Pragma("unroll")                                                       \
        for (int nt = 0; nt < 4; nt++) {                                        \
            MMA_B16(acc[mt][nt], afr[0][mt], bfr[0][nt]);                       \
            MMA_B16(acc[mt][nt], afr[0][mt], bfr[1][nt]);                       \
            MMA_B16(acc[mt][nt], afr[1][mt], bfr[0][nt]);                       \
        }                                                                       \
} while (0)

// ---------------------------------------------------------------------------
// Conv 3x3 (+bias,+ReLU) via mma, cp.async 3-stage pipeline, 144 k-stages.
// ---------------------------------------------------------------------------
#define CONV_FILL(s, bi) do {                                                   \
    size_t awo = (size_t)(s) * 4096 + (co0 + t) * 16;                           \
    uint32_t ahd = (uint32_t)__cvta_generic_to_shared(ASH(bi, 0, t, 0));        \
    uint32_t ald = (uint32_t)__cvta_generic_to_shared(ASH(bi, 1, t, 0));        \
    CPA16(ahd,      g_cw2_hi + awo);                                            \
    CPA16(ahd + 16, g_cw2_hi + awo + 8);                                        \
    CPA16(ald,      g_cw2_lo + awo);                                            \
    CPA16(ald + 16, g_cw2_lo + awo + 8);                                        \
    int r_ = (s) >> 4;                                                          \
    int dy_ = r_ / 3, dx_ = r_ - 3 * dy_;                                       \
    unsigned v_ = ((vmy >> dy_) & 1u) & ((vmx >> dx_) & 1u);                    \
    size_t off_ = fbase + ((size_t)((s) & 15) * Np                              \
                + (size_t)(pix + (dy_ - 1) * W + (dx_ - 1))) * 16 + kh8;        \
    uint32_t bhd = (uint32_t)__cvta_generic_to_shared(BSH(bi, 0, bpx, kh8));    \
    uint32_t bld = (uint32_t)__cvta_generic_to_shared(BSH(bi, 1, bpx, kh8));    \
    CPA16Z(bhd, g_fh + off_, v_);                                               \
    CPA16Z(bld, g_fl + off_, v_);                                               \
} while (0)

__global__ void __launch_bounds__(128) conv_all(const float* __restrict__ bias)
{
    extern __shared__ __nv_bfloat16 gsm[];
    __nv_bfloat16* smA = gsm;                     // 3 * A_ST
    __nv_bfloat16* smB = gsm + 3 * A_ST;          // 3 * B_ST

    int bx = blockIdx.x;
    int lvl = (bx < 169) ? 0 : (bx < 212) ? 1 : (bx < 223) ? 2 : 3;
    int p0 = (bx - c_HTO[lvl]) * 64;
    int W  = c_W[lvl];
    int H  = W;
    int Np = W * W;

    int b   = blockIdx.z;
    int co0 = blockIdx.y * 128;
    int t   = threadIdx.x;
    int lane = t & 31, warp = t >> 5;
    int mo = (warp >> 1) * 64, no = (warp & 1) * 32;

    size_t fbase = (size_t)c_toff[lvl] + (size_t)b * Np * 256;

    int bpx = t >> 1;
    int kh8 = (t & 1) * 8;
    int pix = p0 + bpx;
    bool inp = pix < Np;
    if (!inp) pix = 0;
    int py = pix / W;
    int px = pix - py * W;
    unsigned vmy = ((py > 0) ? 1u : 0u) | 2u | ((py + 1 < H) ? 4u : 0u);
    unsigned vmx = ((px > 0) ? 1u : 0u) | 2u | ((px + 1 < W) ? 4u : 0u);
    if (!inp) vmy = 0u;

    float acc[4][4][4];
#pragma unroll
    for (int i = 0; i < 4; i++)
#pragma unroll
        for (int j = 0; j < 4; j++)
#pragma unroll
            for (int q = 0; q < 4; q++) acc[i][j][q] = 0.f;

    CONV_FILL(0, 0); CPA_COMMIT();
    CONV_FILL(1, 1); CPA_COMMIT();

    for (int s = 0; s < 144; s++) {
        CPA_WAIT1();
        __syncthreads();
        int nf = s + 2;
        if (nf < 144) {
            int bi = nf - (nf / 3) * 3;
            CONV_FILL(nf, bi);
        }
        CPA_COMMIT();
        GEMM_COMPUTE(s - (s / 3) * 3);
    }

    int g = lane >> 2, tg = lane & 3;
#pragma unroll
    for (int mt = 0; mt < 4; mt++) {
        int coA = co0 + mo + mt * 16 + g;
        int coB = coA + 8;
        float bA = __ldg(&bias[coA]);
        float bB = __ldg(&bias[coB]);
        float* opA = g_t + c_toff[lvl] + ((size_t)b * CHN + coA) * Np;
        float* opB = g_t + c_toff[lvl] + ((size_t)b * CHN + coB) * Np;
#pragma unroll
        for (int nt = 0; nt < 4; nt++) {
            int pxo = p0 + no + nt * 8 + tg * 2;
            float* d = acc[mt][nt];
            if (pxo < Np) {
                opA[pxo] = fmaxf(d[0] + bA, 0.f);
                opB[pxo] = fmaxf(d[2] + bB, 0.f);
            }
            if (pxo + 1 < Np) {
                opA[pxo + 1] = fmaxf(d[1] + bA, 0.f);
                opB[pxo + 1] = fmaxf(d[3] + bB, 0.f);
            }
        }
    }
}

// ---------------------------------------------------------------------------
// FC via mma (128x64, 128 thr, split-K 4), cp.async 3-stage, 196 k-stages.
// ---------------------------------------------------------------------------
#define FC_FILL(s, bi) do {                                                     \
    size_t awo = (size_t)(kblk0 + (s)) * 22528 + (m0 + t) * 16;                 \
    uint32_t ahd = (uint32_t)__cvta_generic_to_shared(ASH(bi, 0, t, 0));        \
    uint32_t ald = (uint32_t)__cvta_generic_to_shared(ASH(bi, 1, t, 0));        \
    CPA16(ahd,      g_fw2_hi + awo);                                            \
    CPA16(ahd + 16, g_fw2_hi + awo + 8);                                        \
    CPA16(ald,      g_fw2_lo + awo);                                            \
    CPA16(ald + 16, g_fw2_lo + awo + 8);                                        \
    size_t ro_ = (size_t)(kblk0 + (s)) * 9600 + (size_t)(n0 + bpx) * 16 + kh8;  \
    uint32_t bhd = (uint32_t)__cvta_generic_to_shared(BSH(bi, 0, bpx, kh8));    \
    uint32_t bld = (uint32_t)__cvta_generic_to_shared(BSH(bi, 1, bpx, kh8));    \
    CPA16Z(bhd, g_rfh + ro_, nvalid);                                           \
    CPA16Z(bld, g_rfl + ro_, nvalid);                                           \
} while (0)

__global__ void __launch_bounds__(128) fc_gemm()
{
    extern __shared__ __nv_bfloat16 gsm[];
    __nv_bfloat16* smA = gsm;
    __nv_bfloat16* smB = gsm + 3 * A_ST;

    int m0 = blockIdx.x * 128;
    int n0 = blockIdx.y * 64;
    int kidx = blockIdx.z;
    int kblk0 = kidx * 196;
    int t = threadIdx.x;
    int lane = t & 31, warp = t >> 5;
    int mo = (warp >> 1) * 64, no = (warp & 1) * 32;

    int bpx = t >> 1;
    int kh8 = (t & 1) * 8;
    unsigned nvalid = (n0 + bpx) < 600 ? 1u : 0u;

    float acc[4][4][4];
#pragma unroll
    for (int i = 0; i < 4; i++)
#pragma unroll
        for (int j = 0; j < 4; j++)
#pragma unroll
            for (int q = 0; q < 4; q++) acc[i][j][q] = 0.f;

    FC_FILL(0, 0); CPA_COMMIT();
    FC_FILL(1, 1); CPA_COMMIT();

    for (int s = 0; s < 196; s++) {
        CPA_WAIT1();
        __syncthreads();
        int nf = s + 2;
        if (nf < 196) {
            int bi = nf - (nf / 3) * 3;
            FC_FILL(nf, bi);
        }
        CPA_COMMIT();
        GEMM_COMPUTE(s - (s / 3) * 3);
    }

    int g = lane >> 2, tg = lane & 3;
    float* part = g_fcpart + (size_t)kidx * 600 * 1408;
#pragma unroll
    for (int mt = 0; mt < 4; mt++) {
        int m = m0 + mo + mt * 16 + g;
#pragma unroll
        for (int nt = 0; nt < 4; nt++) {
            int n = n0 + no + nt * 8 + tg * 2;
            float* d = acc[mt][nt];
            if (n < 600) {
                part[(size_t)n * 1408 + m]     = d[0];
                part[(size_t)n * 1408 + m + 8] = d[2];
            }
            if (n + 1 < 600) {
                part[(size_t)(n + 1) * 1408 + m]     = d[1];
                part[(size_t)(n + 1) * 1408 + m + 8] = d[3];
            }
        }
    }
}

__global__ void fc_reduce(const float* __restrict__ fb, float* __restrict__ out)
{
    int i = blockIdx.x * 256 + threadIdx.x;
    if (i >= 600 * 1408) return;
    const int S = 600 * 1408;
    out[i] = ((g_fcpart[i] + g_fcpart[S + i])
            + (g_fcpart[2 * S + i] + g_fcpart[3 * S + i])) + __ldg(&fb[i % 1408]);
}

// ---------------------------------------------------------------------------
// 1x1 heads, all levels
// ---------------------------------------------------------------------------
__global__ void __launch_bounds__(256) head_all(
    const float* __restrict__ cls_w, const float* __restrict__ cls_b,
    const float* __restrict__ bbox_w, const float* __restrict__ bbox_b)
{
    __shared__ float w[15][256];
    __shared__ float red[4][15][65];

    int bx = blockIdx.x;
    int lvl = (bx < 169) ? 0 : (bx < 212) ? 1 : (bx < 223) ? 2 : 3;
    int pt = bx - c_HTO[lvl];
    int Wl = c_W[lvl];
    int Np = Wl * Wl;
    int noff = c_noff[lvl];

    int b = blockIdx.y;
    int t = threadIdx.x;
    for (int i = t; i < 15 * 256; i += 256) {
        int o = i >> 8, c = i & 255;
        w[o][c] = (o < 3) ? cls_w[o * 256 + c] : bbox_w[(o - 3) * 256 + c];
    }
    __syncthreads();

    int pl = t & 63, cq = t >> 6;
    int p = pt * 64 + pl;
    float acc[15];
#pragma unroll
    for (int o = 0; o < 15; o++) acc[o] = 0.f;

    if (p < Np) {
        const float* tb = g_t + c_toff[lvl] + ((size_t)b * CHN + cq * 64) * Np + p;
#pragma unroll 4
        for (int c = 0; c < 64; c++) {
            float v = __ldg(tb + (size_t)c * Np);
#pragma unroll
            for (int o = 0; o < 15; o++) acc[o] = fmaf(w[o][cq * 64 + c], v, acc[o]);
        }
    }
#pragma unroll
    for (int o = 0; o < 15; o++) red[cq][o][pl] = acc[o];
    __syncthreads();

    for (int idx = t; idx < 64 * 15; idx += 256) {
        int pl2 = idx & 63, o = idx >> 6;
        int p2 = pt * 64 + pl2;
        if (p2 >= Np) continue;
        float s = red[0][o][pl2] + red[1][o][pl2] + red[2][o][pl2] + red[3][o][pl2];
        int nb = b * NTOT + noff + p2 * 3;
        if (o < 3) {
            g_logits[nb + o] = s + __ldg(&cls_b[o]);
        } else {
            int oo = o - 3;
            int a = oo >> 2, j = oo & 3;
            g_deltas[(size_t)(nb + a) * 4 + j] = s + __ldg(&bbox_b[oo]);
        }
    }
}

// ---------------------------------------------------------------------------
// Radix top-k select per (batch, level).
// ---------------------------------------------------------------------------
__device__ __forceinline__ unsigned fkey(float f)
{
    unsigned u = __float_as_uint(f);
    return (u & 0x80000000u) ? ~u : (u | 0x80000000u);
}

__global__ void __launch_bounds__(512) topk_select()
{
    int blk = blockIdx.x;
    int b = blk >> 2, lvl = blk & 3;
    int N = c_Nanch[lvl], K = c_K[lvl];
    const float* lg = g_logits + b * NTOT + c_noff[lvl];

    __shared__ unsigned bins[256];
    __shared__ unsigned s_prefix, s_kk, s_cG, s_c1, s_c2;
    int t = threadIdx.x;
    if (t == 0) { s_prefix = 0u; s_kk = (unsigned)K; }
    __syncthreads();

    for (int pass = 3; pass >= 0; pass--) {
        int sh = pass * 8;
        if (t < 256) bins[t] = 0u;
        __syncthreads();
        unsigned prefix = s_prefix;
        unsigned hmask = (pass == 3) ? 0u : (0xFFFFFFFFu << (sh + 8));
        for (int i = t; i < N; i += 512) {
            unsigned key = fkey(lg[i]);
            if ((key & hmask) == prefix)
                atomicAdd(&bins[(key >> sh) & 255u], 1u);
        }
        __syncthreads();
        if (t == 0) {
            unsigned kk = s_kk, cum = 0u;
            int v = 255;
            for (; v > 0; v--) {
                if (cum + bins[v] >= kk) break;
                cum += bins[v];
            }
            s_kk = kk - cum;
            s_prefix = prefix | ((unsigned)v << sh);
        }
        __syncthreads();
    }
    unsigned T = s_prefix;
    if (t == 0) { s_cG = 0u; s_c1 = 0u; s_c2 = 0u; }
    __syncthreads();

    unsigned lc = 0u;
    for (int i = t; i < N; i += 512)
        if (fkey(lg[i]) > T) lc++;
    if (lc) atomicAdd(&s_cG, lc);
    __syncthreads();
    unsigned TG = s_cG;

    int* outn = g_cand_n + b * TOTC + c_cbase[lvl];
    for (int i = t; i < N; i += 512) {
        unsigned key = fkey(lg[i]);
        if (key > T) {
            unsigned s = atomicAdd(&s_c1, 1u);
            outn[s] = i;
        } else if (key == T) {
            unsigned s = TG + atomicAdd(&s_c2, 1u);
            if (s < (unsigned)K) outn[s] = i;
        }
    }
}

// ---------------------------------------------------------------------------
// Decode candidates
// ---------------------------------------------------------------------------
__global__ void __launch_bounds__(256) decode_cand()
{
    int tid = blockIdx.x * 256 + threadIdx.x;
    if (tid >= BATCH * TOTC) return;
    int b = tid / TOTC, c = tid - b * TOTC;
    int lvl = c / 1000; if (lvl > 3) lvl = 3;
    int n = g_cand_n[tid];
    int W = c_W[lvl];
    float stride = c_stride[lvl], size = c_size[lvl];

    int a = n % 3, cell = n / 3;
    int gx = cell % W, gy = cell / W;

    float ratio = (a == 0) ? 0.5f : ((a == 1) ? 1.0f : 2.0f);
    float hr = sqrtf(ratio);
    float wr = 1.0f / hr;
    float ws = wr * size, hs = hr * size;
    float w2 = rintf(ws * 0.5f);
    float h2 = rintf(hs * 0.5f);
    float sx = gx * stride, sy = gy * stride;
    float x1 = sx - w2, y1 = sy - h2, x2 = sx + w2, y2 = sy + h2;

    float wa = x2 - x1, ha = y2 - y1;
    float cxa = x1 + 0.5f * wa, cya = y1 + 0.5f * ha;

    int gi = b * NTOT + c_noff[lvl] + n;
    float score = g_logits[gi];
    const float* d = g_deltas + (size_t)gi * 4;
    float dx = d[0], dy = d[1];
    float dw = fminf(d[2], CLAMPF), dh = fminf(d[3], CLAMPF);
    float cx = dx * wa + cxa, cy = dy * ha + cya;
    float bw = expf(dw) * wa, bh = expf(dh) * ha;
    float bx1 = cx - 0.5f * bw, by1 = cy - 0.5f * bh;
    float bx2 = cx + 0.5f * bw, by2 = cy + 0.5f * bh;
    bx1 = fminf(fmaxf(bx1, 0.f), IMG);
    by1 = fminf(fmaxf(by1, 0.f), IMG);
    bx2 = fminf(fmaxf(bx2, 0.f), IMG);
    by2 = fminf(fmaxf(by2, 0.f), IMG);

    float bws = bx2 - bx1, bhs = by2 - by1;
    bool bad = (bws < 0.001f) || (bhs < 0.001f) || (score < 0.0f);
    g_sc[tid] = bad ? NEGF : score;

    float off = (float)lvl * 4096.0f;
    float* bp = g_box + (size_t)tid * 4;
    bp[0] = bx1; bp[1] = by1; bp[2] = bx2; bp[3] = by2;
    float* op = g_obox + (size_t)tid * 4;
    op[0] = bx1 + off; op[1] = by1 + off; op[2] = bx2 + off; op[3] = by2 + off;
}

// ---------------------------------------------------------------------------
// Greedy NMS (one sync/iter)
// ---------------------------------------------------------------------------
#define NMSTH 512
#define NMSLP 7
#define NMS_SMEM (4 * 3584 * 4 + 300 * 8)

__global__ void __launch_bounds__(NMSTH) nms_kernel()
{
    extern __shared__ float dsm[];
    float* sx1 = dsm;
    float* sy1 = dsm + 3584;
    float* sx2 = dsm + 2 * 3584;
    float* sy2 = dsm + 3 * 3584;
    unsigned long long* sbest = (unsigned long long*)(dsm + 4 * 3584);

    int b = blockIdx.x;
    int t = threadIdx.x;
    const unsigned NEGK = fkey(NEGF);
    const unsigned OKTH = fkey(NEGF * 0.5f);

    unsigned long long kreg[NMSLP];
    float ax[NMSLP], ay[NMSLP], bx2[NMSLP], by2[NMSLP], ar[NMSLP];
#pragma unroll
    for (int l = 0; l < NMSLP; l++) {
        int i = t + l * NMSTH;
        float s;
        if (i < TOTC) {
            s = g_sc[b * TOTC + i];
            const float* bbp = g_obox + (size_t)(b * TOTC + i) * 4;
            ax[l] = bbp[0]; ay[l] = bbp[1]; bx2[l] = bbp[2]; by2[l] = bbp[3];
        } else {
            s = -INFINITY; ax[l] = ay[l] = bx2[l] = by2[l] = 0.f;
        }
        ar[l] = (bx2[l] - ax[l]) * (by2[l] - ay[l]);
        kreg[l] = ((unsigned long long)fkey(s) << 32)
                | (unsigned long long)(0x7FFFFFFFu - (unsigned)i);
        sx1[i] = ax[l]; sy1[i] = ay[l]; sx2[i] = bx2[l]; sy2[i] = by2[l];
    }
    for (int i = t; i < POST; i += NMSTH) sbest[i] = 0ull;
    __syncthreads();

    for (int it = 0; it < POST; it++) {
        unsigned long long key = kreg[0];
#pragma unroll
        for (int l = 1; l < NMSLP; l++) if (kreg[l] > key) key = kreg[l];
#pragma unroll
        for (int o = 16; o; o >>= 1) {
            unsigned long long ok2 = __shfl_down_sync(0xFFFFFFFFu, key, o);
            if (ok2 > key) key = ok2;
        }
        if ((t & 31) == 0) atomicMax(&sbest[it], key);
        __syncthreads();

        unsigned long long bk = sbest[it];
        int j = (int)(0x7FFFFFFFu - (unsigned)(bk & 0xFFFFFFFFull));
        float jx1 = sx1[j], jy1 = sy1[j], jx2 = sx2[j], jy2 = sy2[j];
        float ja = (jx2 - jx1) * (jy2 - jy1);
        bool ok = (unsigned)(bk >> 32) > OKTH;

        if (t == 0) {
            float* rr = g_rois + (size_t)(b * POST + it) * 4;
            if (ok) {
                const float* cb = g_box + (size_t)(b * TOTC + j) * 4;
                rr[0] = cb[0]; rr[1] = cb[1]; rr[2] = cb[2]; rr[3] = cb[3];
            } else {
                rr[0] = 0.f; rr[1] = 0.f; rr[2] = 0.f; rr[3] = 0.f;
            }
        }

        int lo = j - t;
        if (lo >= 0 && (lo & (NMSTH - 1)) == 0) {
            int l = lo >> 9;
            if (l < NMSLP)
                kreg[l] = ((unsigned long long)NEGK << 32)
                        | (unsigned long long)(0x7FFFFFFFu - (unsigned)j);
        }
#pragma unroll
        for (int l = 0; l < NMSLP; l++) {
            float xx1 = fmaxf(jx1, ax[l]),  yy1 = fmaxf(jy1, ay[l]);
            float xx2 = fminf(jx2, bx2[l]), yy2 = fminf(jy2, by2[l]);
            float inter = fmaxf(xx2 - xx1, 0.f) * fmaxf(yy2 - yy1, 0.f);
            float iou = inter / fmaxf(ja + ar[l] - inter, 1e-9f);
            if (iou > 0.7f)
                kreg[l] = ((unsigned long long)NEGK << 32)
                        | (unsigned long long)(0x7FFFFFFFu - (unsigned)(t + l * NMSTH));
        }
    }
}

// ---------------------------------------------------------------------------
// ROI align, smem-staged coalesced blocked writes
// ---------------------------------------------------------------------------
#define ROI_SMEM (2 * 12544 * 2)

__global__ void __launch_bounds__(256) roi_align_kernel()
{
    extern __shared__ __nv_bfloat16 rsm[];
    int roi = blockIdx.x;
    int b = roi / POST;
    int c = threadIdx.x;

    const float* R = g_rois + (size_t)roi * 4;
    const float scale = 0.015625f;
    float x1 = R[0] * scale - 0.5f, y1 = R[1] * scale - 0.5f;
    float x2 = R[2] * scale - 0.5f, y2 = R[3] * scale - 0.5f;

    float acc[49];
#pragma unroll
    for (int i = 0; i < 49; i++) acc[i] = 0.f;

    const float* F = g_ft3 + (size_t)b * 169 * 256 + c;

#pragma unroll
    for (int py = 0; py < 14; py++) {
        float gy = ((float)py + 0.5f) / 14.0f;
        float yy = y1 + gy * (y2 - y1);
        bool vy = (yy >= -1.0f) && (yy <= 13.0f);
        float y = fminf(fmaxf(yy, 0.f), 12.f);
        int y0 = (int)floorf(y);
        int y1i = min(y0 + 1, 12);
        float ly = y - (float)y0;
#pragma unroll
        for (int px = 0; px < 14; px++) {
            float gx = ((float)px + 0.5f) / 14.0f;
            float xx = x1 + gx * (x2 - x1);
            bool vx = (xx >= -1.0f) && (xx <= 13.0f);
            float x = fminf(fmaxf(xx, 0.f), 12.f);
            int x0 = (int)floorf(x);
            int x1i = min(x0 + 1, 12);
            float lx = x - (float)x0;

            float c00 = __ldg(&F[(y0 * 13 + x0) * 256]);
            float c01 = __ldg(&F[(y0 * 13 + x1i) * 256]);
            float c10 = __ldg(&F[(y1i * 13 + x0) * 256]);
            float c11 = __ldg(&F[(y1i * 13 + x1i) * 256]);
            float v = c00 * (1.f - ly) * (1.f - lx) + c01 * (1.f - ly) * lx
                    + c10 * ly * (1.f - lx)        + c11 * ly * lx;
            if (!(vy && vx)) v = 0.f;
            acc[(py >> 1) * 7 + (px >> 1)] += v;
        }
    }

#pragma unroll
    for (int i = 0; i < 49; i++) {
        int k = c * 49 + i;
        __nv_bfloat16 h, l;
        bsplit(acc[i] * 0.25f, h, l);
        rsm[k] = h;
        rsm[12544 + k] = l;
    }
    __syncthreads();

    for (int kb = c; kb < 784; kb += 256) {
        size_t off = (size_t)kb * 9600 + (size_t)roi * 16;
        *(uint4*)(g_rfh + off)     = *(const uint4*)&rsm[kb * 16];
        *(uint4*)(g_rfh + off + 8) = *(const uint4*)&rsm[kb * 16 + 8];
        *(uint4*)(g_rfl + off)     = *(const uint4*)&rsm[12544 + kb * 16];
        *(uint4*)(g_rfl + off + 8) = *(const uint4*)&rsm[12544 + kb * 16 + 8];
    }
}

// ---------------------------------------------------------------------------
// Launch (conv_all at process-launch slot 3 for the ncu capture)
// ---------------------------------------------------------------------------
extern "C" void kernel_launch(void* const* d_in, const int* in_sizes, int n_in,
                              void* d_out, int out_size)
{
    const float* f0     = (const float*)d_in[0];
    const float* f1     = (const float*)d_in[1];
    const float* f2     = (const float*)d_in[2];
    const float* f3     = (const float*)d_in[3];
    const float* conv_w = (const float*)d_in[4];
    const float* conv_b = (const float*)d_in[5];
    const float* cls_w  = (const float*)d_in[6];
    const float* cls_b  = (const float*)d_in[7];
    const float* bbox_w = (const float*)d_in[8];
    const float* bbox_b = (const float*)d_in[9];
    const float* fc_w   = (const float*)d_in[10];
    const float* fc_b   = (const float*)d_in[11];

    static int attr_set = 0;
    if (!attr_set) {
        cudaFuncSetAttribute(nms_kernel,
                             cudaFuncAttributeMaxDynamicSharedMemorySize, NMS_SMEM);
        cudaFuncSetAttribute(roi_align_kernel,
                             cudaFuncAttributeMaxDynamicSharedMemorySize, ROI_SMEM);
        cudaFuncSetAttribute(conv_all,
                             cudaFuncAttributeMaxDynamicSharedMemorySize, GEMM_SMEM);
        cudaFuncSetAttribute(fc_gemm,
                             cudaFuncAttributeMaxDynamicSharedMemorySize, GEMM_SMEM);
        attr_set = 1;
    }

    prep_wconv<<<256, 256>>>(conv_w);                                 // 0
    prep_feat<<<dim3(451, 8, BATCH), 256>>>(f0, f1, f2, f3);          // 1
    prep_fw<<<(784 * 1408 + 255) / 256, 256>>>(fc_w);                 // 2
    conv_all<<<dim3(226, 2, BATCH), 128, GEMM_SMEM>>>(conv_b);        // 3 <- profile
    prep_ft3<<<(BATCH * 169 * 256 + 255) / 256, 256>>>(f3);           // 4
    head_all<<<dim3(226, BATCH), 256>>>(cls_w, cls_b, bbox_w, bbox_b);// 5
    topk_select<<<8, 512>>>();                                        // 6
    decode_cand<<<(BATCH * TOTC + 255) / 256, 256>>>();               // 7
    nms_kernel<<<BATCH, NMSTH, NMS_SMEM>>>();                         // 8
    roi_align_kernel<<<BATCH * POST, 256, ROI_SMEM>>>();              // 9
    fc_gemm<<<dim3(11, 10, 4), 128, GEMM_SMEM>>>();                   // 10
    fc_reduce<<<(600 * 1408 + 255) / 256, 256>>>(fc_b, (float*)d_out);// 11
}

// round 17
// speedup vs baseline: 1.1348x; 1.1348x over previous
#include <cuda_runtime.h>
#include <cuda_bf16.h>
#include <stdint.h>
#include <math.h>

// ---------------------------------------------------------------------------
// Fixed problem shapes
// ---------------------------------------------------------------------------
#define BATCH 2
#define CHN   256
#define NTOT  43095
#define TOTC  3507
#define POST  300
#define NEGF  (-1e30f)
#define CLAMPF 4.135166556742356f
#define IMG   832.0f

__device__ __constant__ int   c_W[4]      = {104, 52, 26, 13};
__device__ __constant__ int   c_Nanch[4]  = {32448, 8112, 2028, 507};
__device__ __constant__ int   c_noff[4]   = {0, 32448, 40560, 42588};
__device__ __constant__ int   c_K[4]      = {1000, 1000, 1000, 507};
__device__ __constant__ int   c_cbase[4]  = {0, 1000, 2000, 3000};
__device__ __constant__ float c_stride[4] = {8.f, 16.f, 32.f, 64.f};
__device__ __constant__ float c_size[4]   = {32.f, 64.f, 128.f, 256.f};
__device__ __constant__ int   c_HTO[4]    = {0, 169, 212, 223};
__device__ __constant__ int   c_FTO[4]    = {0, 338, 423, 445};
__device__ __constant__ int   c_toff[4]   = {0, 5537792, 6922240, 7268352};

// ---------------------------------------------------------------------------
// Static device scratch
// ---------------------------------------------------------------------------
__device__ __align__(16) float g_t[7354880];
__device__ __align__(16) __nv_bfloat16 g_fh[7354880];
__device__ __align__(16) __nv_bfloat16 g_fl[7354880];
__device__ __align__(16) float g_ft3[BATCH * 169 * CHN];
__device__ float g_logits[BATCH * NTOT];
__device__ float g_deltas[BATCH * NTOT * 4];
__device__ int   g_cand_n[BATCH * TOTC];
__device__ float g_sc[BATCH * TOTC];
__device__ float g_box[BATCH * TOTC * 4];
__device__ float g_obox[BATCH * TOTC * 4];
__device__ float g_rois[BATCH * POST * 4];
__device__ __align__(16) __nv_bfloat16 g_rfh[784 * 600 * 16];
__device__ __align__(16) __nv_bfloat16 g_rfl[784 * 600 * 16];
__device__ __align__(16) float g_fcpart[4 * 600 * 1408];
__device__ __align__(16) __nv_bfloat16 g_cw2_hi[144 * 256 * 16];
__device__ __align__(16) __nv_bfloat16 g_cw2_lo[144 * 256 * 16];
__device__ __align__(16) __nv_bfloat16 g_fw2_hi[784 * 1408 * 16];
__device__ __align__(16) __nv_bfloat16 g_fw2_lo[784 * 1408 * 16];

union U8 { __nv_bfloat16 b[8]; uint4 u; };

__device__ __forceinline__ void bsplit(float x, __nv_bfloat16& h, __nv_bfloat16& l)
{
    h = __float2bfloat16_rn(x);
    l = __float2bfloat16_rn(x - __bfloat162float(h));
}

// ---------------------------------------------------------------------------
// Prep kernels
// ---------------------------------------------------------------------------
__global__ void prep_wconv(const float* __restrict__ cw)
{
    int co = blockIdx.x;
    int t = threadIdx.x;
#pragma unroll
    for (int j = 0; j < 9; j++) {
        int kp = j * 256 + t;
        int ci = kp & 255, r = kp >> 8;
        float v = cw[co * 2304 + ci * 9 + r];
        size_t d = (size_t)(kp >> 4) * 4096 + co * 16 + (kp & 15);
        __nv_bfloat16 h, l;
        bsplit(v, h, l);
        g_cw2_hi[d] = h;
        g_cw2_lo[d] = l;
    }
}

__global__ void prep_fw(const float* __restrict__ fw)
{
    int idx = blockIdx.x * 256 + threadIdx.x;
    if (idx >= 784 * 1408) return;
    int kblk = idx / 1408;
    int m = idx - kblk * 1408;
    const float4* p = (const float4*)(fw + (size_t)m * 12544 + kblk * 16);
    float4 v0 = p[0], v1 = p[1], v2 = p[2], v3 = p[3];
    float xs[16] = {v0.x, v0.y, v0.z, v0.w, v1.x, v1.y, v1.z, v1.w,
                    v2.x, v2.y, v2.z, v2.w, v3.x, v3.y, v3.z, v3.w};
    U8 h0, l0, h1, l1;
#pragma unroll
    for (int i = 0; i < 8; i++) bsplit(xs[i], h0.b[i], l0.b[i]);
#pragma unroll
    for (int i = 0; i < 8; i++) bsplit(xs[8 + i], h1.b[i], l1.b[i]);
    size_t d = (size_t)kblk * 22528 + m * 16;
    *(uint4*)(g_fw2_hi + d) = h0.u;  *(uint4*)(g_fw2_hi + d + 8) = h1.u;
    *(uint4*)(g_fw2_lo + d) = l0.u;  *(uint4*)(g_fw2_lo + d + 8) = l1.u;
}

__global__ void prep_feat(
    const float* __restrict__ f0, const float* __restrict__ f1,
    const float* __restrict__ f2, const float* __restrict__ f3)
{
    __shared__ float tile[32][33];
    int bx = blockIdx.x;
    int lvl = (bx < 338) ? 0 : (bx < 423) ? 1 : (bx < 445) ? 2 : 3;
    int pix0 = (bx - c_FTO[lvl]) * 32;
    int W = c_W[lvl];
    int Np = W * W;
    const float* in = (lvl == 0) ? f0 : (lvl == 1) ? f1 : (lvl == 2) ? f2 : f3;

    int cg32 = blockIdx.y;
    int b    = blockIdx.z;
    int t    = threadIdx.x;
    int tx = t & 31, ty = t >> 5;

#pragma unroll
    for (int r = 0; r < 4; r++) {
        int cl = ty + r * 8;
        int pix = pix0 + tx;
        float v = (pix < Np) ? in[((size_t)b * 256 + cg32 * 32 + cl) * Np + pix] : 0.f;
        tile[cl][tx] = v;
    }
    __syncthreads();
    size_t lb = (size_t)c_toff[lvl] + (size_t)b * Np * 256;
#pragma unroll
    for (int r = 0; r < 4; r++) {
        int pl = ty + r * 8;
        int pix = pix0 + pl;
        if (pix < Np) {
            float v = tile[tx][pl];
            __nv_bfloat16 h, l;
            bsplit(v, h, l);
            int ch = cg32 * 32 + tx;
            size_t off = lb + ((size_t)(ch >> 4) * Np + pix) * 16 + (ch & 15);
            g_fh[off] = h;
            g_fl[off] = l;
        }
    }
}

__global__ void prep_ft3(const float* __restrict__ f3)
{
    int idx = blockIdx.x * 256 + threadIdx.x;
    if (idx >= BATCH * 169 * 256) return;
    int c = idx & 255;
    int p = (idx >> 8) % 169;
    int b = idx / (169 * 256);
    g_ft3[idx] = f3[(b * 256 + c) * 169 + p];
}

// ---------------------------------------------------------------------------
// mma machinery (warp tile 64x32, BK=16, bf16-split, fp32 accum)
// ---------------------------------------------------------------------------
#define LDSM4(r0, r1, r2, r3, addr)                                             \
    asm volatile("ldmatrix.sync.aligned.m8n8.x4.shared.b16 {%0,%1,%2,%3},[%4];" \
                 : "=r"(r0), "=r"(r1), "=r"(r2), "=r"(r3) : "r"(addr))

#define MMA_B16(d, a, b)                                                        \
    asm volatile("mma.sync.aligned.m16n8k16.row.col.f32.bf16.bf16.f32 "         \
                 "{%0,%1,%2,%3},{%4,%5,%6,%7},{%8,%9},{%0,%1,%2,%3};"           \
                 : "+f"(d[0]), "+f"(d[1]), "+f"(d[2]), "+f"(d[3])               \
                 : "r"(a[0]), "r"(a[1]), "r"(a[2]), "r"(a[3]),                  \
                   "r"(b[0]), "r"(b[1]))

#define GEMM_COMPUTE(bf) do {                                                   \
    uint32_t afr[2][4][4];                                                      \
    uint32_t bfr[2][4][2];                                                      \
    _Pragma("unroll")                                                           \
    for (int h = 0; h < 2; h++) {                                               \
        _Pragma("unroll")                                                       \
        for (int mt = 0; mt < 4; mt++) {                                        \
            uint32_t ad = (uint32_t)__cvta_generic_to_shared(                   \
                &Ash[bf][h][mo + mt * 16 + (lane & 15)][(lane >> 4) * 8]);      \
            LDSM4(afr[h][mt][0], afr[h][mt][1], afr[h][mt][2], afr[h][mt][3], ad); \
        }                                                                       \
        _Pragma("unroll")                                                       \
        for (int np = 0; np < 2; np++) {                                        \
            uint32_t bd = (uint32_t)__cvta_generic_to_shared(                   \
                &Bsh[bf][h][no + np * 16 + (lane & 7) + ((lane & 16) >> 1)][lane & 8]); \
            LDSM4(bfr[h][np * 2][0], bfr[h][np * 2][1],                         \
                  bfr[h][np * 2 + 1][0], bfr[h][np * 2 + 1][1], bd);            \
        }                                                                       \
    }                                                                           \
    _Pragma("unroll")                                                           \
    for (int mt = 0; mt < 4; mt++)                                              \
        _Pragma("unroll")                                                       \
        for (int nt = 0; nt < 4; nt++) {                                        \
            MMA_B16(acc[mt][nt], afr[0][mt], bfr[0][nt]);                       \
            MMA_B16(acc[mt][nt], afr[0][mt], bfr[1][nt]);                       \
            MMA_B16(acc[mt][nt], afr[1][mt], bfr[0][nt]);                       \
        }                                                                       \
} while (0)

// ---------------------------------------------------------------------------
// Conv 3x3 (+bias,+ReLU) via mma. K' = tap*256+ci, 144 stages of 16.
// LDG-staged double buffering (L1-friendly; cp.async.cg regressed this).
// ---------------------------------------------------------------------------
#define CONV_FILL(s, bf) do {                                                   \
    size_t awo = (size_t)(s) * 4096 + (co0 + t) * 16;                           \
    uint4 ah0 = *(const uint4*)(g_cw2_hi + awo);                                \
    uint4 ah1 = *(const uint4*)(g_cw2_hi + awo + 8);                            \
    uint4 al0 = *(const uint4*)(g_cw2_lo + awo);                                \
    uint4 al1 = *(const uint4*)(g_cw2_lo + awo + 8);                            \
    *(uint4*)&Ash[bf][0][t][0] = ah0; *(uint4*)&Ash[bf][0][t][8] = ah1;         \
    *(uint4*)&Ash[bf][1][t][0] = al0; *(uint4*)&Ash[bf][1][t][8] = al1;         \
    int r_ = (s) >> 4;                                                          \
    int dy_ = r_ / 3, dx_ = r_ - 3 * dy_;                                       \
    bool v_ = ((vmy >> dy_) & 1u) && ((vmx >> dx_) & 1u);                       \
    size_t off_ = fbase + ((size_t)((s) & 15) * Np                              \
                + (size_t)(pix + (dy_ - 1) * W + (dx_ - 1))) * 16 + kh8;        \
    uint4 hu = v_ ? *(const uint4*)(g_fh + off_) : make_uint4(0, 0, 0, 0);      \
    uint4 lu = v_ ? *(const uint4*)(g_fl + off_) : make_uint4(0, 0, 0, 0);      \
    *(uint4*)&Bsh[bf][0][bpx][kh8] = hu;                                        \
    *(uint4*)&Bsh[bf][1][bpx][kh8] = lu;                                        \
} while (0)

__global__ void __launch_bounds__(128) conv_all(const float* __restrict__ bias)
{
    __shared__ __align__(16) __nv_bfloat16 Ash[2][2][128][24];
    __shared__ __align__(16) __nv_bfloat16 Bsh[2][2][64][24];

    int bx = blockIdx.x;
    int lvl = (bx < 169) ? 0 : (bx < 212) ? 1 : (bx < 223) ? 2 : 3;
    int p0 = (bx - c_HTO[lvl]) * 64;
    int W  = c_W[lvl];
    int H  = W;
    int Np = W * W;

    int b   = blockIdx.z;
    int co0 = blockIdx.y * 128;
    int t   = threadIdx.x;
    int lane = t & 31, warp = t >> 5;
    int mo = (warp >> 1) * 64, no = (warp & 1) * 32;

    size_t fbase = (size_t)c_toff[lvl] + (size_t)b * Np * 256;

    int bpx = t >> 1;
    int kh8 = (t & 1) * 8;
    int pix = p0 + bpx;
    bool inp = pix < Np;
    if (!inp) pix = 0;
    int py = pix / W;
    int px = pix - py * W;
    unsigned vmy = ((py > 0) ? 1u : 0u) | 2u | ((py + 1 < H) ? 4u : 0u);
    unsigned vmx = ((px > 0) ? 1u : 0u) | 2u | ((px + 1 < W) ? 4u : 0u);
    if (!inp) vmy = 0u;

    float acc[4][4][4];
#pragma unroll
    for (int i = 0; i < 4; i++)
#pragma unroll
        for (int j = 0; j < 4; j++)
#pragma unroll
            for (int q = 0; q < 4; q++) acc[i][j][q] = 0.f;

    CONV_FILL(0, 0);
    __syncthreads();

    int bf = 0;
#pragma unroll 2
    for (int s = 1; s < 144; s++) {
        CONV_FILL(s, bf ^ 1);
        GEMM_COMPUTE(bf);
        __syncthreads();
        bf ^= 1;
    }
    GEMM_COMPUTE(bf);

    int g = lane >> 2, tg = lane & 3;
#pragma unroll
    for (int mt = 0; mt < 4; mt++) {
        int coA = co0 + mo + mt * 16 + g;
        int coB = coA + 8;
        float bA = __ldg(&bias[coA]);
        float bB = __ldg(&bias[coB]);
        float* opA = g_t + c_toff[lvl] + ((size_t)b * CHN + coA) * Np;
        float* opB = g_t + c_toff[lvl] + ((size_t)b * CHN + coB) * Np;
#pragma unroll
        for (int nt = 0; nt < 4; nt++) {
            int pxo = p0 + no + nt * 8 + tg * 2;
            float* d = acc[mt][nt];
            if (pxo < Np) {
                opA[pxo] = fmaxf(d[0] + bA, 0.f);
                opB[pxo] = fmaxf(d[2] + bB, 0.f);
            }
            if (pxo + 1 < Np) {
                opA[pxo + 1] = fmaxf(d[1] + bA, 0.f);
                opB[pxo + 1] = fmaxf(d[3] + bB, 0.f);
            }
        }
    }
}

// ---------------------------------------------------------------------------
// FC via mma (128x64, 128 thr, split-K 4), LDG-staged double buffering.
// ---------------------------------------------------------------------------
#define FC_FILL(s, bf) do {                                                     \
    size_t awo = (size_t)(kblk0 + (s)) * 22528 + (m0 + t) * 16;                 \
    uint4 ah0 = *(const uint4*)(g_fw2_hi + awo);                                \
    uint4 ah1 = *(const uint4*)(g_fw2_hi + awo + 8);                            \
    uint4 al0 = *(const uint4*)(g_fw2_lo + awo);                                \
    uint4 al1 = *(const uint4*)(g_fw2_lo + awo + 8);                            \
    *(uint4*)&Ash[bf][0][t][0] = ah0; *(uint4*)&Ash[bf][0][t][8] = ah1;         \
    *(uint4*)&Ash[bf][1][t][0] = al0; *(uint4*)&Ash[bf][1][t][8] = al1;         \
    size_t ro_ = (size_t)(kblk0 + (s)) * 9600 + (size_t)(n0 + bpx) * 16 + kh8;  \
    uint4 hu = nvalid ? *(const uint4*)(g_rfh + ro_) : make_uint4(0, 0, 0, 0);  \
    uint4 lu = nvalid ? *(const uint4*)(g_rfl + ro_) : make_uint4(0, 0, 0, 0);  \
    *(uint4*)&Bsh[bf][0][bpx][kh8] = hu;                                        \
    *(uint4*)&Bsh[bf][1][bpx][kh8] = lu;                                        \
} while (0)

__global__ void __launch_bounds__(128) fc_gemm()
{
    __shared__ __align__(16) __nv_bfloat16 Ash[2][2][128][24];
    __shared__ __align__(16) __nv_bfloat16 Bsh[2][2][64][24];

    int m0 = blockIdx.x * 128;
    int n0 = blockIdx.y * 64;
    int kidx = blockIdx.z;
    int kblk0 = kidx * 196;
    int t = threadIdx.x;
    int lane = t & 31, warp = t >> 5;
    int mo = (warp >> 1) * 64, no = (warp & 1) * 32;

    int bpx = t >> 1;
    int kh8 = (t & 1) * 8;
    bool nvalid = (n0 + bpx) < 600;

    float acc[4][4][4];
#pragma unroll
    for (int i = 0; i < 4; i++)
#pragma unroll
        for (int j = 0; j < 4; j++)
#pragma unroll
            for (int q = 0; q < 4; q++) acc[i][j][q] = 0.f;

    FC_FILL(0, 0);
    __syncthreads();

    int bf = 0;
#pragma unroll 2
    for (int s = 1; s < 196; s++) {
        FC_FILL(s, bf ^ 1);
        GEMM_COMPUTE(bf);
        __syncthreads();
        bf ^= 1;
    }
    GEMM_COMPUTE(bf);

    int g = lane >> 2, tg = lane & 3;
    float* part = g_fcpart + (size_t)kidx * 600 * 1408;
#pragma unroll
    for (int mt = 0; mt < 4; mt++) {
        int m = m0 + mo + mt * 16 + g;
#pragma unroll
        for (int nt = 0; nt < 4; nt++) {
            int n = n0 + no + nt * 8 + tg * 2;
            float* d = acc[mt][nt];
            if (n < 600) {
                part[(size_t)n * 1408 + m]     = d[0];
                part[(size_t)n * 1408 + m + 8] = d[2];
            }
            if (n + 1 < 600) {
                part[(size_t)(n + 1) * 1408 + m]     = d[1];
                part[(size_t)(n + 1) * 1408 + m + 8] = d[3];
            }
        }
    }
}

__global__ void fc_reduce(const float* __restrict__ fb, float* __restrict__ out)
{
    int i = blockIdx.x * 256 + threadIdx.x;
    if (i >= 600 * 1408) return;
    const int S = 600 * 1408;
    out[i] = ((g_fcpart[i] + g_fcpart[S + i])
            + (g_fcpart[2 * S + i] + g_fcpart[3 * S + i])) + __ldg(&fb[i % 1408]);
}

// ---------------------------------------------------------------------------
// 1x1 heads, all levels
// ---------------------------------------------------------------------------
__global__ void __launch_bounds__(256) head_all(
    const float* __restrict__ cls_w, const float* __restrict__ cls_b,
    const float* __restrict__ bbox_w, const float* __restrict__ bbox_b)
{
    __shared__ float w[15][256];
    __shared__ float red[4][15][65];

    int bx = blockIdx.x;
    int lvl = (bx < 169) ? 0 : (bx < 212) ? 1 : (bx < 223) ? 2 : 3;
    int pt = bx - c_HTO[lvl];
    int Wl = c_W[lvl];
    int Np = Wl * Wl;
    int noff = c_noff[lvl];

    int b = blockIdx.y;
    int t = threadIdx.x;
    for (int i = t; i < 15 * 256; i += 256) {
        int o = i >> 8, c = i & 255;
        w[o][c] = (o < 3) ? cls_w[o * 256 + c] : bbox_w[(o - 3) * 256 + c];
    }
    __syncthreads();

    int pl = t & 63, cq = t >> 6;
    int p = pt * 64 + pl;
    float acc[15];
#pragma unroll
    for (int o = 0; o < 15; o++) acc[o] = 0.f;

    if (p < Np) {
        const float* tb = g_t + c_toff[lvl] + ((size_t)b * CHN + cq * 64) * Np + p;
#pragma unroll 4
        for (int c = 0; c < 64; c++) {
            float v = __ldg(tb + (size_t)c * Np);
#pragma unroll
            for (int o = 0; o < 15; o++) acc[o] = fmaf(w[o][cq * 64 + c], v, acc[o]);
        }
    }
#pragma unroll
    for (int o = 0; o < 15; o++) red[cq][o][pl] = acc[o];
    __syncthreads();

    for (int idx = t; idx < 64 * 15; idx += 256) {
        int pl2 = idx & 63, o = idx >> 6;
        int p2 = pt * 64 + pl2;
        if (p2 >= Np) continue;
        float s = red[0][o][pl2] + red[1][o][pl2] + red[2][o][pl2] + red[3][o][pl2];
        int nb = b * NTOT + noff + p2 * 3;
        if (o < 3) {
            g_logits[nb + o] = s + __ldg(&cls_b[o]);
        } else {
            int oo = o - 3;
            int a = oo >> 2, j = oo & 3;
            g_deltas[(size_t)(nb + a) * 4 + j] = s + __ldg(&bbox_b[oo]);
        }
    }
}

// ---------------------------------------------------------------------------
// Radix top-k select per (batch, level).
// ---------------------------------------------------------------------------
__device__ __forceinline__ unsigned fkey(float f)
{
    unsigned u = __float_as_uint(f);
    return (u & 0x80000000u) ? ~u : (u | 0x80000000u);
}

__global__ void __launch_bounds__(512) topk_select()
{
    int blk = blockIdx.x;
    int b = blk >> 2, lvl = blk & 3;
    int N = c_Nanch[lvl], K = c_K[lvl];
    const float* lg = g_logits + b * NTOT + c_noff[lvl];

    __shared__ unsigned bins[256];
    __shared__ unsigned s_prefix, s_kk, s_cG, s_c1, s_c2;
    int t = threadIdx.x;
    if (t == 0) { s_prefix = 0u; s_kk = (unsigned)K; }
    __syncthreads();

    for (int pass = 3; pass >= 0; pass--) {
        int sh = pass * 8;
        if (t < 256) bins[t] = 0u;
        __syncthreads();
        unsigned prefix = s_prefix;
        unsigned hmask = (pass == 3) ? 0u : (0xFFFFFFFFu << (sh + 8));
        for (int i = t; i < N; i += 512) {
            unsigned key = fkey(lg[i]);
            if ((key & hmask) == prefix)
                atomicAdd(&bins[(key >> sh) & 255u], 1u);
        }
        __syncthreads();
        if (t == 0) {
            unsigned kk = s_kk, cum = 0u;
            int v = 255;
            for (; v > 0; v--) {
                if (cum + bins[v] >= kk) break;
                cum += bins[v];
            }
            s_kk = kk - cum;
            s_prefix = prefix | ((unsigned)v << sh);
        }
        __syncthreads();
    }
    unsigned T = s_prefix;
    if (t == 0) { s_cG = 0u; s_c1 = 0u; s_c2 = 0u; }
    __syncthreads();

    unsigned lc = 0u;
    for (int i = t; i < N; i += 512)
        if (fkey(lg[i]) > T) lc++;
    if (lc) atomicAdd(&s_cG, lc);
    __syncthreads();
    unsigned TG = s_cG;

    int* outn = g_cand_n + b * TOTC + c_cbase[lvl];
    for (int i = t; i < N; i += 512) {
        unsigned key = fkey(lg[i]);
        if (key > T) {
            unsigned s = atomicAdd(&s_c1, 1u);
            outn[s] = i;
        } else if (key == T) {
            unsigned s = TG + atomicAdd(&s_c2, 1u);
            if (s < (unsigned)K) outn[s] = i;
        }
    }
}

// ---------------------------------------------------------------------------
// Decode candidates
// ---------------------------------------------------------------------------
__global__ void __launch_bounds__(256) decode_cand()
{
    int tid = blockIdx.x * 256 + threadIdx.x;
    if (tid >= BATCH * TOTC) return;
    int b = tid / TOTC, c = tid - b * TOTC;
    int lvl = c / 1000; if (lvl > 3) lvl = 3;
    int n = g_cand_n[tid];
    int W = c_W[lvl];
    float stride = c_stride[lvl], size = c_size[lvl];

    int a = n % 3, cell = n / 3;
    int gx = cell % W, gy = cell / W;

    float ratio = (a == 0) ? 0.5f : ((a == 1) ? 1.0f : 2.0f);
    float hr = sqrtf(ratio);
    float wr = 1.0f / hr;
    float ws = wr * size, hs = hr * size;
    float w2 = rintf(ws * 0.5f);
    float h2 = rintf(hs * 0.5f);
    float sx = gx * stride, sy = gy * stride;
    float x1 = sx - w2, y1 = sy - h2, x2 = sx + w2, y2 = sy + h2;

    float wa = x2 - x1, ha = y2 - y1;
    float cxa = x1 + 0.5f * wa, cya = y1 + 0.5f * ha;

    int gi = b * NTOT + c_noff[lvl] + n;
    float score = g_logits[gi];
    const float* d = g_deltas + (size_t)gi * 4;
    float dx = d[0], dy = d[1];
    float dw = fminf(d[2], CLAMPF), dh = fminf(d[3], CLAMPF);
    float cx = dx * wa + cxa, cy = dy * ha + cya;
    float bw = expf(dw) * wa, bh = expf(dh) * ha;
    float bx1 = cx - 0.5f * bw, by1 = cy - 0.5f * bh;
    float bx2 = cx + 0.5f * bw, by2 = cy + 0.5f * bh;
    bx1 = fminf(fmaxf(bx1, 0.f), IMG);
    by1 = fminf(fmaxf(by1, 0.f), IMG);
    bx2 = fminf(fmaxf(bx2, 0.f), IMG);
    by2 = fminf(fmaxf(by2, 0.f), IMG);

    float bws = bx2 - bx1, bhs = by2 - by1;
    bool bad = (bws < 0.001f) || (bhs < 0.001f) || (score < 0.0f);
    g_sc[tid] = bad ? NEGF : score;

    float off = (float)lvl * 4096.0f;
    float* bp = g_box + (size_t)tid * 4;
    bp[0] = bx1; bp[1] = by1; bp[2] = bx2; bp[3] = by2;
    float* op = g_obox + (size_t)tid * 4;
    op[0] = bx1 + off; op[1] = by1 + off; op[2] = bx2 + off; op[3] = by2 + off;
}

// ---------------------------------------------------------------------------
// Greedy NMS (one sync/iter)
// ---------------------------------------------------------------------------
#define NMSTH 512
#define NMSLP 7
#define NMS_SMEM (4 * 3584 * 4 + 300 * 8)

__global__ void __launch_bounds__(NMSTH) nms_kernel()
{
    extern __shared__ float dsm[];
    float* sx1 = dsm;
    float* sy1 = dsm + 3584;
    float* sx2 = dsm + 2 * 3584;
    float* sy2 = dsm + 3 * 3584;
    unsigned long long* sbest = (unsigned long long*)(dsm + 4 * 3584);

    int b = blockIdx.x;
    int t = threadIdx.x;
    const unsigned NEGK = fkey(NEGF);
    const unsigned OKTH = fkey(NEGF * 0.5f);

    unsigned long long kreg[NMSLP];
    float ax[NMSLP], ay[NMSLP], bx2[NMSLP], by2[NMSLP], ar[NMSLP];
#pragma unroll
    for (int l = 0; l < NMSLP; l++) {
        int i = t + l * NMSTH;
        float s;
        if (i < TOTC) {
            s = g_sc[b * TOTC + i];
            const float* bbp = g_obox + (size_t)(b * TOTC + i) * 4;
            ax[l] = bbp[0]; ay[l] = bbp[1]; bx2[l] = bbp[2]; by2[l] = bbp[3];
        } else {
            s = -INFINITY; ax[l] = ay[l] = bx2[l] = by2[l] = 0.f;
        }
        ar[l] = (bx2[l] - ax[l]) * (by2[l] - ay[l]);
        kreg[l] = ((unsigned long long)fkey(s) << 32)
                | (unsigned long long)(0x7FFFFFFFu - (unsigned)i);
        sx1[i] = ax[l]; sy1[i] = ay[l]; sx2[i] = bx2[l]; sy2[i] = by2[l];
    }
    for (int i = t; i < POST; i += NMSTH) sbest[i] = 0ull;
    __syncthreads();

    for (int it = 0; it < POST; it++) {
        unsigned long long key = kreg[0];
#pragma unroll
        for (int l = 1; l < NMSLP; l++) if (kreg[l] > key) key = kreg[l];
#pragma unroll
        for (int o = 16; o; o >>= 1) {
            unsigned long long ok2 = __shfl_down_sync(0xFFFFFFFFu, key, o);
            if (ok2 > key) key = ok2;
        }
        if ((t & 31) == 0) atomicMax(&sbest[it], key);
        __syncthreads();

        unsigned long long bk = sbest[it];
        int j = (int)(0x7FFFFFFFu - (unsigned)(bk & 0xFFFFFFFFull));
        float jx1 = sx1[j], jy1 = sy1[j], jx2 = sx2[j], jy2 = sy2[j];
        float ja = (jx2 - jx1) * (jy2 - jy1);
        bool ok = (unsigned)(bk >> 32) > OKTH;

        if (t == 0) {
            float* rr = g_rois + (size_t)(b * POST + it) * 4;
            if (ok) {
                const float* cb = g_box + (size_t)(b * TOTC + j) * 4;
                rr[0] = cb[0]; rr[1] = cb[1]; rr[2] = cb[2]; rr[3] = cb[3];
            } else {
                rr[0] = 0.f; rr[1] = 0.f; rr[2] = 0.f; rr[3] = 0.f;
            }
        }

        int lo = j - t;
        if (lo >= 0 && (lo & (NMSTH - 1)) == 0) {
            int l = lo >> 9;
            if (l < NMSLP)
                kreg[l] = ((unsigned long long)NEGK << 32)
                        | (unsigned long long)(0x7FFFFFFFu - (unsigned)j);
        }
#pragma unroll
        for (int l = 0; l < NMSLP; l++) {
            float xx1 = fmaxf(jx1, ax[l]),  yy1 = fmaxf(jy1, ay[l]);
            float xx2 = fminf(jx2, bx2[l]), yy2 = fminf(jy2, by2[l]);
            float inter = fmaxf(xx2 - xx1, 0.f) * fmaxf(yy2 - yy1, 0.f);
            float iou = inter / fmaxf(ja + ar[l] - inter, 1e-9f);
            if (iou > 0.7f)
                kreg[l] = ((unsigned long long)NEGK << 32)
                        | (unsigned long long)(0x7FFFFFFFu - (unsigned)(t + l * NMSTH));
        }
    }
}

// ---------------------------------------------------------------------------
// ROI align, smem-staged coalesced blocked writes
// ---------------------------------------------------------------------------
#define ROI_SMEM (2 * 12544 * 2)

__global__ void __launch_bounds__(256) roi_align_kernel()
{
    extern __shared__ __nv_bfloat16 rsm[];
    int roi = blockIdx.x;
    int b = roi / POST;
    int c = threadIdx.x;

    const float* R = g_rois + (size_t)roi * 4;
    const float scale = 0.015625f;
    float x1 = R[0] * scale - 0.5f, y1 = R[1] * scale - 0.5f;
    float x2 = R[2] * scale - 0.5f, y2 = R[3] * scale - 0.5f;

    float acc[49];
#pragma unroll
    for (int i = 0; i < 49; i++) acc[i] = 0.f;

    const float* F = g_ft3 + (size_t)b * 169 * 256 + c;

#pragma unroll
    for (int py = 0; py < 14; py++) {
        float gy = ((float)py + 0.5f) / 14.0f;
        float yy = y1 + gy * (y2 - y1);
        bool vy = (yy >= -1.0f) && (yy <= 13.0f);
        float y = fminf(fmaxf(yy, 0.f), 12.f);
        int y0 = (int)floorf(y);
        int y1i = min(y0 + 1, 12);
        float ly = y - (float)y0;
#pragma unroll
        for (int px = 0; px < 14; px++) {
            float gx = ((float)px + 0.5f) / 14.0f;
            float xx = x1 + gx * (x2 - x1);
            bool vx = (xx >= -1.0f) && (xx <= 13.0f);
            float x = fminf(fmaxf(xx, 0.f), 12.f);
            int x0 = (int)floorf(x);
            int x1i = min(x0 + 1, 12);
            float lx = x - (float)x0;

            float c00 = __ldg(&F[(y0 * 13 + x0) * 256]);
            float c01 = __ldg(&F[(y0 * 13 + x1i) * 256]);
            float c10 = __ldg(&F[(y1i * 13 + x0) * 256]);
            float c11 = __ldg(&F[(y1i * 13 + x1i) * 256]);
            float v = c00 * (1.f - ly) * (1.f - lx) + c01 * (1.f - ly) * lx
                    + c10 * ly * (1.f - lx)        + c11 * ly * lx;
            if (!(vy && vx)) v = 0.f;
            acc[(py >> 1) * 7 + (px >> 1)] += v;
        }
    }

#pragma unroll
    for (int i = 0; i < 49; i++) {
        int k = c * 49 + i;
        __nv_bfloat16 h, l;
        bsplit(acc[i] * 0.25f, h, l);
        rsm[k] = h;
        rsm[12544 + k] = l;
    }
    __syncthreads();

    for (int kb = c; kb < 784; kb += 256) {
        size_t off = (size_t)kb * 9600 + (size_t)roi * 16;
        *(uint4*)(g_rfh + off)     = *(const uint4*)&rsm[kb * 16];
        *(uint4*)(g_rfh + off + 8) = *(const uint4*)&rsm[kb * 16 + 8];
        *(uint4*)(g_rfl + off)     = *(const uint4*)&rsm[12544 + kb * 16];
        *(uint4*)(g_rfl + off + 8) = *(const uint4*)&rsm[12544 + kb * 16 + 8];
    }
}

// ---------------------------------------------------------------------------
// Launch (conv_all at process-launch slot 3 for the ncu capture)
// ---------------------------------------------------------------------------
extern "C" void kernel_launch(void* const* d_in, const int* in_sizes, int n_in,
                              void* d_out, int out_size)
{
    const float* f0     = (const float*)d_in[0];
    const float* f1     = (const float*)d_in[1];
    const float* f2     = (const float*)d_in[2];
    const float* f3     = (const float*)d_in[3];
    const float* conv_w = (const float*)d_in[4];
    const float* conv_b = (const float*)d_in[5];
    const float* cls_w  = (const float*)d_in[6];
    const float* cls_b  = (const float*)d_in[7];
    const float* bbox_w = (const float*)d_in[8];
    const float* bbox_b = (const float*)d_in[9];
    const float* fc_w   = (const float*)d_in[10];
    const float* fc_b   = (const float*)d_in[11];

    static int attr_set = 0;
    if (!attr_set) {
        cudaFuncSetAttribute(nms_kernel,
                             cudaFuncAttributeMaxDynamicSharedMemorySize, NMS_SMEM);
        cudaFuncSetAttribute(roi_align_kernel,
                             cudaFuncAttributeMaxDynamicSharedMemorySize, ROI_SMEM);
        attr_set = 1;
    }

    prep_wconv<<<256, 256>>>(conv_w);                                 // 0
    prep_feat<<<dim3(451, 8, BATCH), 256>>>(f0, f1, f2, f3);          // 1
    prep_fw<<<(784 * 1408 + 255) / 256, 256>>>(fc_w);                 // 2
    conv_all<<<dim3(226, 2, BATCH), 128>>>(conv_b);                   // 3 <- profile
    prep_ft3<<<(BATCH * 169 * 256 + 255) / 256, 256>>>(f3);           // 4
    head_all<<<dim3(226, BATCH), 256>>>(cls_w, cls_b, bbox_w, bbox_b);// 5
    topk_select<<<8, 512>>>();                                        // 6
    decode_cand<<<(BATCH * TOTC + 255) / 256, 256>>>();               // 7
    nms_kernel<<<BATCH, NMSTH, NMS_SMEM>>>();                         // 8
    roi_align_kernel<<<BATCH * POST, 256, ROI_SMEM>>>();              // 9
    fc_gemm<<<dim3(11, 10, 4), 128>>>();                              // 10
    fc_reduce<<<(600 * 1408 + 255) / 256, 256>>>(fc_b, (float*)d_out);// 11
}